// round 16
// baseline (speedup 1.0000x reference)
#include <cuda_runtime.h>
#include <cuda_fp16.h>
#include <cstdint>
#include <math.h>

#define B_   4
#define H_   64
#define W_   128
#define DM_  256
#define NH_  8
#define NPIX (B_*H_*W_)      // 32768
#define HW_  (H_*W_)         // 8192
#define NOAP 256
#define KDIM 256
#define NDIM 256
#define LSTRIDE (NPIX*DM_)

#define BS_STRIDE 136
#define BS_BUF (16*BS_STRIDE)
#define STAGES 4

// ------------------------- scratch (device globals; no allocation) -------------------------
__device__ __align__(256) __half   g_sfh  [2*LSTRIDE + 256];
__device__ __align__(256) __half   g_feath[NPIX*DM_];
__device__ __align__(256) float    g_offA [NPIX*NOAP];
__device__ __align__(256) float    g_Weff [DM_*NOAP];
__device__ __align__(256) float    g_beff [NOAP];
__device__ __align__(256) unsigned g_WkP  [128*NDIM];
__device__ __align__(256) unsigned g_WmP  [128*NDIM];
__device__ __align__(256) unsigned g_WeffP[128*NDIM];

__device__ __forceinline__ unsigned pack2(float x, float y) {
    __half2 h = __floats2half2_rn(x, y);
    return *reinterpret_cast<unsigned*>(&h);
}

// --------- Weff = Wq @ [Wo | Wa | 0] (blocks 0..255), beff = bq@Wcat + [bo|ba|0] (block 256)
__global__ void wbeff_kernel(const float* __restrict__ Wq, const float* __restrict__ Wo,
                             const float* __restrict__ Wa, const float* __restrict__ bq,
                             const float* __restrict__ bo, const float* __restrict__ ba)
{
    __shared__ float wq[DM_];
    const int r = blockIdx.x;
    const int c = threadIdx.x;
    const bool isBias = (r == DM_);
    wq[c] = isBias ? bq[c] : Wq[r * DM_ + c];
    __syncthreads();
    float acc = 0.f;
    if (c < 128) {
        for (int k = 0; k < DM_; k++) acc += wq[k] * Wo[k * 128 + c];
        if (isBias) acc += bo[c];
    } else if (c < 192) {
        const int cc = c - 128;
        for (int k = 0; k < DM_; k++) acc += wq[k] * Wa[k * 64 + cc];
        if (isBias) acc += ba[cc];
    }
    if (isBias) g_beff[c] = (c < 192) ? acc : 0.f;
    else        g_Weff[r * NOAP + c] = (c < 192) ? acc : 0.f;
}

__global__ void pack_weights(const float* __restrict__ Wk, const float* __restrict__ Wm)
{
    const int p = blockIdx.x;
    const int n = threadIdx.x;
    const int w = blockIdx.y;
    const float* W = (w == 0) ? Wk : (w == 1) ? Wm : g_Weff;
    unsigned v = pack2(W[(2 * p) * NDIM + n], W[(2 * p + 1) * NDIM + n]);
    unsigned* D = (w == 0) ? g_WkP : (w == 1) ? g_WmP : g_WeffP;
    D[p * NDIM + n] = v;
}

// ------------------------- cp.async helpers -------------------------
__device__ __forceinline__ void cpasync16(void* smem_ptr, const void* gptr) {
    unsigned saddr = (unsigned)__cvta_generic_to_shared(smem_ptr);
    asm volatile("cp.async.cg.shared.global [%0], [%1], 16;" :: "r"(saddr), "l"(gptr));
}
#define CP_COMMIT() asm volatile("cp.async.commit_group;")
#define CP_WAIT2()  asm volatile("cp.async.wait_group 2;" ::: "memory")

// ------------------------- persistent FP16 tensor-core GEMM core ---------------------------
// CTA 128x128x32, 8 warps, warp 32x64 = 2x8 m16n8k16. 4-stage cp.async ring flowing
// continuously across multiple M-tiles per CTA (single-wave persistent grid).

template<typename T> struct GT;
template<> struct GT<float>  { static const int AW = 36; static const int ABUF = 128*36; };
template<> struct GT<__half> { static const int AW = 20; static const int ABUF = 128*20; };

__device__ __forceinline__ void mma_f16(float c[4], const unsigned a[4], const unsigned b[2]) {
    asm volatile(
        "mma.sync.aligned.m16n8k16.row.col.f32.f16.f16.f32 "
        "{%0,%1,%2,%3}, {%4,%5,%6,%7}, {%8,%9}, {%0,%1,%2,%3};"
        : "+f"(c[0]), "+f"(c[1]), "+f"(c[2]), "+f"(c[3])
        : "r"(a[0]), "r"(a[1]), "r"(a[2]), "r"(a[3]), "r"(b[0]), "r"(b[1]));
}

template<typename TIN, typename TOUT>
__device__ __forceinline__
void gemm_core(const TIN* __restrict__ A, const unsigned* __restrict__ Bpk,
               const float* __restrict__ bias, TOUT* __restrict__ C,
               unsigned* __restrict__ smem, int colBase, int bx, int step, int cnt)
{
    const int STAGE_W = GT<TIN>::ABUF + BS_BUF;

    const int tid  = threadIdx.x;
    const int lane = tid & 31;
    const int wid  = tid >> 5;
    const int g    = lane >> 2;
    const int tg   = lane & 3;
    const int warpRow = (wid & 3) * 32;
    const int warpCol = (wid >> 2) * 64;

#define ISSUE(buf, mrow, kt)                                                                \
    {                                                                                       \
        const TIN* Ap_ = A + (size_t)(mrow) * 128 * KDIM;                                   \
        unsigned* aS = smem + (buf) * STAGE_W;                                              \
        unsigned* bS = aS + GT<TIN>::ABUF;                                                  \
        if (sizeof(TIN) == 4) {                                                             \
            _Pragma("unroll")                                                               \
            for (int i = 0; i < 4; i++) {                                                   \
                int idx = tid + 256 * i, row = idx >> 3, ch = idx & 7;                      \
                cpasync16(aS + row * 36 + ch * 4,                                           \
                          (const char*)Ap_ + ((size_t)row * KDIM + (kt) * 32 + ch * 4) * 4);\
            }                                                                               \
        } else {                                                                            \
            _Pragma("unroll")                                                               \
            for (int i = 0; i < 2; i++) {                                                   \
                int idx = tid + 256 * i, row = idx >> 2, ch = idx & 3;                      \
                cpasync16(aS + row * 20 + ch * 4,                                           \
                          (const char*)Ap_ + ((size_t)row * KDIM + (kt) * 32 + ch * 8) * 2);\
            }                                                                               \
        }                                                                                   \
        _Pragma("unroll")                                                                   \
        for (int i = 0; i < 2; i++) {                                                       \
            int idx = tid + 256 * i, prow = idx >> 5, ch = idx & 31;                        \
            cpasync16(bS + prow * BS_STRIDE + ch * 4,                                       \
                      Bpk + ((kt) * 16 + prow) * NDIM + colBase + ch * 4);                  \
        }                                                                                   \
    }

    float acc[2][8][4];
#pragma unroll
    for (int mt = 0; mt < 2; mt++)
#pragma unroll
        for (int nt = 0; nt < 8; nt++)
#pragma unroll
            for (int j = 0; j < 4; j++) acc[mt][nt][j] = 0.f;

    // prologue: first 3 chunks of tile 0
    ISSUE(0, bx, 0); CP_COMMIT();
    ISSUE(1, bx, 1); CP_COMMIT();
    ISSUE(2, bx, 2); CP_COMMIT();

    for (int ti = 0; ti < cnt; ti++) {
        const int m = bx + step * ti;

#pragma unroll
        for (int kt = 0; kt < 8; kt++) {
            CP_WAIT2();
            __syncthreads();

            const int cur = kt & 3;                 // (ti*8+kt) & 3 == kt & 3
            const unsigned* aU = smem + cur * STAGE_W;
            const unsigned* Bs = aU + GT<TIN>::ABUF;
            const float*    Af = (const float*)aU;

#pragma unroll
            for (int s = 0; s < 2; s++) {
                unsigned af[2][4];
                if (sizeof(TIN) == 4) {
                    const int kb = s * 16 + 2 * tg;
#pragma unroll
                    for (int mt = 0; mt < 2; mt++) {
                        const int r0 = warpRow + mt * 16 + g;
                        float2 v0 = *(const float2*)(Af + r0 * 36 + kb);
                        float2 v1 = *(const float2*)(Af + (r0 + 8) * 36 + kb);
                        float2 v2 = *(const float2*)(Af + r0 * 36 + kb + 8);
                        float2 v3 = *(const float2*)(Af + (r0 + 8) * 36 + kb + 8);
                        af[mt][0] = pack2(v0.x, v0.y);
                        af[mt][1] = pack2(v1.x, v1.y);
                        af[mt][2] = pack2(v2.x, v2.y);
                        af[mt][3] = pack2(v3.x, v3.y);
                    }
                } else {
                    const int kc0 = s * 8;
#pragma unroll
                    for (int mt = 0; mt < 2; mt++) {
                        const int r0 = warpRow + mt * 16 + g;
                        af[mt][0] = aU[r0 * 20 + kc0 + tg];
                        af[mt][1] = aU[(r0 + 8) * 20 + kc0 + tg];
                        af[mt][2] = aU[r0 * 20 + kc0 + 4 + tg];
                        af[mt][3] = aU[(r0 + 8) * 20 + kc0 + 4 + tg];
                    }
                }
                const int kc0 = s * 8;
                unsigned bf[8][2];
#pragma unroll
                for (int nt = 0; nt < 8; nt++) {
                    const int c0 = warpCol + nt * 8 + g;
                    bf[nt][0] = Bs[(kc0 + tg) * BS_STRIDE + c0];
                    bf[nt][1] = Bs[(kc0 + 4 + tg) * BS_STRIDE + c0];
                }
#pragma unroll
                for (int mt = 0; mt < 2; mt++)
#pragma unroll
                    for (int nt = 0; nt < 8; nt++)
                        mma_f16(acc[mt][nt], af[mt], bf[nt]);
            }

            // issue chunk c+3 (continues into next tile)
            const bool doIssue = (kt < 5) || (ti + 1 < cnt);
            if (doIssue) {
                const int nti = ti + (kt >= 5);
                ISSUE((kt + 3) & 3, bx + step * nti, (kt + 3) & 7);
            }
            CP_COMMIT();
        }

        // epilogue for tile m (overlaps next tile's in-flight loads)
        const int rowBase = m * 128;
#pragma unroll
        for (int mt = 0; mt < 2; mt++) {
            const int row = rowBase + warpRow + mt * 16 + g;
#pragma unroll
            for (int nt = 0; nt < 8; nt++) {
                const int col = colBase + warpCol + nt * 8 + tg * 2;
                const float2 bv = *(const float2*)(bias + col);
                const float v0 = acc[mt][nt][0] + bv.x, v1 = acc[mt][nt][1] + bv.y;
                const float v2 = acc[mt][nt][2] + bv.x, v3 = acc[mt][nt][3] + bv.y;
                if (sizeof(TOUT) == 2) {
                    __half* Ch = (__half*)C;
                    const int h = col >> 5, cc = col & 31;
                    const int b0 = row >> 13, rem0 = row & (HW_ - 1);
                    const int b1 = (row + 8) >> 13, rem1 = (row + 8) & (HW_ - 1);
                    *(unsigned*)(Ch + ((size_t)(b0 * NH_ + h) * HW_ + rem0) * 32 + cc) = pack2(v0, v1);
                    *(unsigned*)(Ch + ((size_t)(b1 * NH_ + h) * HW_ + rem1) * 32 + cc) = pack2(v2, v3);
                } else {
                    float* Cf = (float*)C;
                    *(float2*)(Cf + (size_t)row * NDIM + col) = make_float2(v0, v1);
                    *(float2*)(Cf + (size_t)(row + 8) * NDIM + col) = make_float2(v2, v3);
                }
#pragma unroll
                for (int j = 0; j < 4; j++) acc[mt][nt][j] = 0.f;
            }
        }
    }
#undef ISSUE
}

// persistent heads: grid (48, 6); group = blockIdx.y: col = g&1, z = g>>1; single wave.
__global__ __launch_bounds__(256, 2)
void gemm_heads(const float* __restrict__ query, const float* __restrict__ beff,
                float* __restrict__ offA,
                const float* __restrict__ keys0, const float* __restrict__ keys1,
                const float* __restrict__ bk,
                __half* __restrict__ sfh0, __half* __restrict__ sfh1)
{
    extern __shared__ __align__(16) unsigned smem_dyn[];
    const int bx = blockIdx.x;                       // slot 0..47
    const int colBase = (blockIdx.y & 1) * 128;
    const int z = blockIdx.y >> 1;
    const int cnt = (256 - bx + 47) / 48;            // tiles: bx + 48*i
    if (z == 0)      gemm_core<float, float >(query, g_WeffP, beff, offA, smem_dyn, colBase, bx, 48, cnt);
    else if (z == 1) gemm_core<float, __half>(keys0, g_WkP, bk, sfh0, smem_dyn, colBase, bx, 48, cnt);
    else             gemm_core<float, __half>(keys1, g_WkP, bk, sfh1, smem_dyn, colBase, bx, 48, cnt);
}

// persistent out: grid (128, 2); each CTA does tiles bx and bx+128.
__global__ __launch_bounds__(256, 2)
void gemm_out(const float* __restrict__ bias, float* __restrict__ C)
{
    extern __shared__ __align__(16) unsigned smem_dyn[];
    gemm_core<__half, float>(g_feath, g_WmP, bias, C, smem_dyn,
                             (int)blockIdx.y * 128, (int)blockIdx.x, 128, 2);
}

#define SMEM_HEADS (STAGES*(GT<float >::ABUF + BS_BUF)*4)
#define SMEM_OUT   (STAGES*(GT<__half>::ABUF + BS_BUF)*4)

// ------------------------- deformable sampling: two-phase, head-major gathers ---------------
__global__ __launch_bounds__(256)
void sample_kernel(const float* __restrict__ refp)
{
    __shared__ float s_w [4][NH_][8][4];   // (w00, w10, w01, w11): [side][row] pairs
    __shared__ int   s_ix[4][NH_][8][2];

    const int blk = blockIdx.x;
    const int tid = threadIdx.x;

    {
        const int j   = tid & 7;
        const int h   = (tid >> 3) & 7;
        const int sub = tid >> 6;
        const int pixel = blk * 4 + sub;
        const int b = pixel >> 13;
        const int rem = pixel & (HW_ - 1);
        // torch .repeat quirk: ref for bh-index n = b*NH+h is ref_point[n % B]
        const int rb = (b * NH_ + h) % B_;
        const float ry = refp[(rb * HW_ + rem) * 2 + 0];
        const float rx = refp[(rb * HW_ + rem) * 2 + 1];

        const float lgj = g_offA[(size_t)pixel * NOAP + 128 + h * 8 + j];
        float mx = lgj;
#pragma unroll
        for (int o = 4; o; o >>= 1) mx = fmaxf(mx, __shfl_xor_sync(0xffffffffu, mx, o, 8));
        const float e = expf(lgj - mx);
        float s = e;
#pragma unroll
        for (int o = 4; o; o >>= 1) s += __shfl_xor_sync(0xffffffffu, s, o, 8);
        const float w = e / s;

        const float offy = g_offA[(size_t)pixel * NOAP + h * 16 + j * 2 + 0];
        const float offx = g_offA[(size_t)pixel * NOAP + h * 16 + j * 2 + 1];
        const float py = (ry + offy) * ((float)H_ / (float)(H_ - 1)) - 0.5f;
        const float px = (rx + offx) * ((float)W_ / (float)(W_ - 1)) - 0.5f;
        const float fy = floorf(py), fx = floorf(px);
        const int y0 = (int)fy, x0 = (int)fx;
        const float wy1 = py - fy, wx1 = px - fx;
        const float wy0 = 1.f - wy1, wx0 = 1.f - wx1;
        const bool yv0 = (y0 >= 0) && (y0 < H_);
        const bool yv1 = (y0 + 1 >= 0) && (y0 + 1 < H_);
        const bool xv0 = (x0 >= 0) && (x0 < W_);
        const bool xv1 = (x0 + 1 >= 0) && (x0 + 1 < W_);
        const int y0c = min(max(y0, 0), H_ - 1), y1c = min(max(y0 + 1, 0), H_ - 1);
        const int xb  = min(max(x0, -1), W_ - 1);
        const int l = j >> 2;
        const int bh = (b * NH_ + h) * HW_;
        const int loff = l * LSTRIDE;
        s_ix[sub][h][j][0] = loff + (bh + y0c * W_ + xb) * 32;
        s_ix[sub][h][j][1] = loff + (bh + y1c * W_ + xb) * 32;
        s_w [sub][h][j][0] = (yv0 && xv0) ? w * wy0 * wx0 : 0.f;
        s_w [sub][h][j][1] = (yv1 && xv0) ? w * wy1 * wx0 : 0.f;
        s_w [sub][h][j][2] = (yv0 && xv1) ? w * wy0 * wx1 : 0.f;
        s_w [sub][h][j][3] = (yv1 && xv1) ? w * wy1 * wx1 : 0.f;
    }
    __syncthreads();

    const int sub = tid >> 6;
    const int h = (tid >> 3) & 7;
    const int e = tid & 7;
    const int pixel = blk * 4 + sub;
    const bool hi = (e >= 4);
    const int ce = e & 3;
    const int ws = hi ? 2 : 0;                 // side-indexed weight pair

    const __half* sfh = g_sfh + 32;

    float acc[8];
#pragma unroll
    for (int i = 0; i < 8; i++) acc[i] = 0.f;

#pragma unroll
    for (int j = 0; j < 8; j++) {
        const float2 wv = *(const float2*)(&s_w[sub][h][j][ws]);
        const int2   i2 = *(const int2*)(s_ix[sub][h][j]);
        const uint4 u0 = *(const uint4*)(sfh + i2.x + e * 8);
        const uint4 u1 = *(const uint4*)(sfh + i2.y + e * 8);
#pragma unroll
        for (int c = 0; c < 4; c++) {
            const float2 f0 = __half22float2(*(const __half2*)(&(&u0.x)[c]));
            const float2 f1 = __half22float2(*(const __half2*)(&(&u1.x)[c]));
            acc[2 * c + 0] += wv.x * f0.x + wv.y * f1.x;
            acc[2 * c + 1] += wv.x * f0.y + wv.y * f1.y;
        }
    }

    unsigned out[4];
#pragma unroll
    for (int c = 0; c < 4; c++) {
        const float s0 = acc[2 * c + 0] + __shfl_xor_sync(0xffffffffu, acc[2 * c + 0], 4);
        const float s1 = acc[2 * c + 1] + __shfl_xor_sync(0xffffffffu, acc[2 * c + 1], 4);
        out[c] = pack2(s0, s1);
    }
    if (!hi) {
        *(uint4*)(g_feath + (size_t)pixel * DM_ + h * 32 + ce * 8)
            = make_uint4(out[0], out[1], out[2], out[3]);
    }
}

// ------------------------- launch -------------------------
extern "C" void kernel_launch(void* const* d_in, const int* in_sizes, int n_in,
                              void* d_out, int out_size)
{
    const float* query = (const float*)d_in[0];
    const float* keys0 = (const float*)d_in[1];
    const float* keys1 = (const float*)d_in[2];
    const float* refp  = (const float*)d_in[3];
    const float* Wq = (const float*)d_in[4];
    const float* bq = (const float*)d_in[5];
    const float* Wk = (const float*)d_in[6];
    const float* bk = (const float*)d_in[7];
    const float* Wo = (const float*)d_in[8];
    const float* bo = (const float*)d_in[9];
    const float* Wa = (const float*)d_in[10];
    const float* ba = (const float*)d_in[11];
    const float* Wm = (const float*)d_in[12];
    const float* bm = (const float*)d_in[13];
    float* out = (float*)d_out;

    __half* sfh;
    float *offA, *beff;
    cudaGetSymbolAddress((void**)&sfh,  g_sfh);
    cudaGetSymbolAddress((void**)&offA, g_offA);
    cudaGetSymbolAddress((void**)&beff, g_beff);
    __half* sfh0 = sfh + 32;
    __half* sfh1 = sfh + 32 + LSTRIDE;

    cudaFuncSetAttribute(gemm_heads, cudaFuncAttributeMaxDynamicSharedMemorySize, SMEM_HEADS);
    cudaFuncSetAttribute(gemm_out,   cudaFuncAttributeMaxDynamicSharedMemorySize, SMEM_OUT);

    wbeff_kernel<<<DM_ + 1, 256>>>(Wq, Wo, Wa, bq, bo, ba);

    dim3 gp(128, 3);
    pack_weights<<<gp, 256>>>(Wk, Wm);

    dim3 gh(48, 6);                       // persistent, single wave
    gemm_heads<<<gh, 256, SMEM_HEADS>>>(query, beff, offA, keys0, keys1, bk, sfh0, sfh1);

    sample_kernel<<<NPIX / 4, 256>>>(refp);

    dim3 gg(128, 2);                      // persistent, single wave
    gemm_out<<<gg, 256, SMEM_OUT>>>(bm, out);

    (void)in_sizes; (void)n_in; (void)out_size;
}

// round 17
// speedup vs baseline: 1.0656x; 1.0656x over previous
#include <cuda_runtime.h>
#include <cuda_fp16.h>
#include <cstdint>
#include <math.h>

#define B_   4
#define H_   64
#define W_   128
#define DM_  256
#define NH_  8
#define NPIX (B_*H_*W_)      // 32768
#define HW_  (H_*W_)         // 8192
#define NOAP 256
#define KDIM 256
#define NDIM 256
#define LSTRIDE (NPIX*DM_)

#define BS_STRIDE 136
#define BS_BUF (16*BS_STRIDE)
#define STAGES 4

// ------------------------- scratch (device globals; no allocation) -------------------------
__device__ __align__(256) __half   g_sfh  [2*LSTRIDE + 256];
__device__ __align__(256) __half   g_feath[NPIX*DM_];
__device__ __align__(256) float    g_offA [NPIX*NOAP];
__device__ __align__(256) float    g_beff [NOAP];
__device__ __align__(256) unsigned g_WkP  [128*NDIM];
__device__ __align__(256) unsigned g_WmP  [128*NDIM];
__device__ __align__(256) unsigned g_WeffP[128*NDIM];

__device__ __forceinline__ unsigned pack2(float x, float y) {
    __half2 h = __floats2half2_rn(x, y);
    return *reinterpret_cast<unsigned*>(&h);
}

// --------- fused prep: Weff pairs -> WeffP (blocks 0..127), beff (block 128),
//           Wk pack (129..256), Wm pack (257..384)
__global__ void prep_kernel(const float* __restrict__ Wq, const float* __restrict__ Wo,
                            const float* __restrict__ Wa, const float* __restrict__ bq,
                            const float* __restrict__ bo, const float* __restrict__ ba,
                            const float* __restrict__ Wk, const float* __restrict__ Wm)
{
    const int bx = blockIdx.x;
    const int c  = threadIdx.x;
    if (bx < 128) {
        __shared__ float wq0[DM_], wq1[DM_];
        wq0[c] = Wq[(2 * bx) * DM_ + c];
        wq1[c] = Wq[(2 * bx + 1) * DM_ + c];
        __syncthreads();
        float a0 = 0.f, a1 = 0.f;
        if (c < 128) {
            for (int k = 0; k < DM_; k++) {
                a0 += wq0[k] * Wo[k * 128 + c];
                a1 += wq1[k] * Wo[k * 128 + c];
            }
        } else if (c < 192) {
            const int cc = c - 128;
            for (int k = 0; k < DM_; k++) {
                a0 += wq0[k] * Wa[k * 64 + cc];
                a1 += wq1[k] * Wa[k * 64 + cc];
            }
        }
        if (c >= 192) { a0 = 0.f; a1 = 0.f; }
        g_WeffP[bx * NDIM + c] = pack2(a0, a1);
    } else if (bx == 128) {
        __shared__ float bqs[DM_];
        bqs[c] = bq[c];
        __syncthreads();
        float acc = 0.f;
        if (c < 128) {
            for (int k = 0; k < DM_; k++) acc += bqs[k] * Wo[k * 128 + c];
            acc += bo[c];
        } else if (c < 192) {
            const int cc = c - 128;
            for (int k = 0; k < DM_; k++) acc += bqs[k] * Wa[k * 64 + cc];
            acc += ba[cc];
        }
        g_beff[c] = (c < 192) ? acc : 0.f;
    } else if (bx < 257) {
        const int p = bx - 129;
        g_WkP[p * NDIM + c] = pack2(Wk[(2 * p) * NDIM + c], Wk[(2 * p + 1) * NDIM + c]);
    } else {
        const int p = bx - 257;
        g_WmP[p * NDIM + c] = pack2(Wm[(2 * p) * NDIM + c], Wm[(2 * p + 1) * NDIM + c]);
    }
}

// ------------------------- cp.async helpers -------------------------
__device__ __forceinline__ void cpasync16(void* smem_ptr, const void* gptr) {
    unsigned saddr = (unsigned)__cvta_generic_to_shared(smem_ptr);
    asm volatile("cp.async.cg.shared.global [%0], [%1], 16;" :: "r"(saddr), "l"(gptr));
}
#define CP_COMMIT() asm volatile("cp.async.commit_group;")
#define CP_WAIT2()  asm volatile("cp.async.wait_group 2;" ::: "memory")

// ------------------------- FP16 tensor-core GEMM core --------------------------------------
// CTA 128x128x32, 8 warps, warp 32x64 = 2x8 m16n8k16. 4-stage cp.async ring.
// TOUT=__half => head-major sf scatter epilogue.

template<typename T> struct GT;
template<> struct GT<float>  { static const int AW = 36; static const int ABUF = 128*36; };
template<> struct GT<__half> { static const int AW = 20; static const int ABUF = 128*20; };

__device__ __forceinline__ void mma_f16(float c[4], const unsigned a[4], const unsigned b[2]) {
    asm volatile(
        "mma.sync.aligned.m16n8k16.row.col.f32.f16.f16.f32 "
        "{%0,%1,%2,%3}, {%4,%5,%6,%7}, {%8,%9}, {%0,%1,%2,%3};"
        : "+f"(c[0]), "+f"(c[1]), "+f"(c[2]), "+f"(c[3])
        : "r"(a[0]), "r"(a[1]), "r"(a[2]), "r"(a[3]), "r"(b[0]), "r"(b[1]));
}

template<typename TIN, typename TOUT>
__device__ __forceinline__
void gemm_core(const TIN* __restrict__ A, const unsigned* __restrict__ Bpk,
               const float* __restrict__ bias, TOUT* __restrict__ C,
               unsigned* __restrict__ smem)
{
    const int STAGE_W = GT<TIN>::ABUF + BS_BUF;

    const int tid  = threadIdx.x;
    const int lane = tid & 31;
    const int wid  = tid >> 5;
    const int g    = lane >> 2;
    const int tg   = lane & 3;
    const int warpRow = (wid & 3) * 32;
    const int warpCol = (wid >> 2) * 64;
    const int rowBase = blockIdx.y * 128;
    const int colBase = blockIdx.x * 128;

    const TIN* Ap = A + (size_t)rowBase * KDIM;

#define ISSUE(buf, kt)                                                                      \
    {                                                                                       \
        unsigned* aS = smem + (buf) * STAGE_W;                                              \
        unsigned* bS = aS + GT<TIN>::ABUF;                                                  \
        if (sizeof(TIN) == 4) {                                                             \
            _Pragma("unroll")                                                               \
            for (int i = 0; i < 4; i++) {                                                   \
                int idx = tid + 256 * i, row = idx >> 3, ch = idx & 7;                      \
                cpasync16(aS + row * 36 + ch * 4,                                           \
                          (const char*)Ap + ((size_t)row * KDIM + (kt) * 32 + ch * 4) * 4); \
            }                                                                               \
        } else {                                                                            \
            _Pragma("unroll")                                                               \
            for (int i = 0; i < 2; i++) {                                                   \
                int idx = tid + 256 * i, row = idx >> 2, ch = idx & 3;                      \
                cpasync16(aS + row * 20 + ch * 4,                                           \
                          (const char*)Ap + ((size_t)row * KDIM + (kt) * 32 + ch * 8) * 2); \
            }                                                                               \
        }                                                                                   \
        _Pragma("unroll")                                                                   \
        for (int i = 0; i < 2; i++) {                                                       \
            int idx = tid + 256 * i, prow = idx >> 5, ch = idx & 31;                        \
            cpasync16(bS + prow * BS_STRIDE + ch * 4,                                       \
                      Bpk + ((kt) * 16 + prow) * NDIM + colBase + ch * 4);                  \
        }                                                                                   \
    }

    float acc[2][8][4];
#pragma unroll
    for (int mt = 0; mt < 2; mt++)
#pragma unroll
        for (int nt = 0; nt < 8; nt++)
#pragma unroll
            for (int j = 0; j < 4; j++) acc[mt][nt][j] = 0.f;

    ISSUE(0, 0); CP_COMMIT();
    ISSUE(1, 1); CP_COMMIT();
    ISSUE(2, 2); CP_COMMIT();

    const int TILES = KDIM / 32;
#pragma unroll
    for (int kt = 0; kt < TILES; kt++) {
        CP_WAIT2();
        __syncthreads();

        const int cur = kt & 3;
        const unsigned* aU = smem + cur * STAGE_W;
        const unsigned* Bs = aU + GT<TIN>::ABUF;
        const float*    Af = (const float*)aU;

#pragma unroll
        for (int s = 0; s < 2; s++) {
            unsigned af[2][4];
            if (sizeof(TIN) == 4) {
                const int kb = s * 16 + 2 * tg;
#pragma unroll
                for (int mt = 0; mt < 2; mt++) {
                    const int r0 = warpRow + mt * 16 + g;
                    float2 v0 = *(const float2*)(Af + r0 * 36 + kb);
                    float2 v1 = *(const float2*)(Af + (r0 + 8) * 36 + kb);
                    float2 v2 = *(const float2*)(Af + r0 * 36 + kb + 8);
                    float2 v3 = *(const float2*)(Af + (r0 + 8) * 36 + kb + 8);
                    af[mt][0] = pack2(v0.x, v0.y);
                    af[mt][1] = pack2(v1.x, v1.y);
                    af[mt][2] = pack2(v2.x, v2.y);
                    af[mt][3] = pack2(v3.x, v3.y);
                }
            } else {
                const int kc0 = s * 8;
#pragma unroll
                for (int mt = 0; mt < 2; mt++) {
                    const int r0 = warpRow + mt * 16 + g;
                    af[mt][0] = aU[r0 * 20 + kc0 + tg];
                    af[mt][1] = aU[(r0 + 8) * 20 + kc0 + tg];
                    af[mt][2] = aU[r0 * 20 + kc0 + 4 + tg];
                    af[mt][3] = aU[(r0 + 8) * 20 + kc0 + 4 + tg];
                }
            }
            const int kc0 = s * 8;
            unsigned bf[8][2];
#pragma unroll
            for (int nt = 0; nt < 8; nt++) {
                const int c0 = warpCol + nt * 8 + g;
                bf[nt][0] = Bs[(kc0 + tg) * BS_STRIDE + c0];
                bf[nt][1] = Bs[(kc0 + 4 + tg) * BS_STRIDE + c0];
            }
#pragma unroll
            for (int mt = 0; mt < 2; mt++)
#pragma unroll
                for (int nt = 0; nt < 8; nt++)
                    mma_f16(acc[mt][nt], af[mt], bf[nt]);
        }

        if (kt + 3 < TILES) ISSUE((kt + 3) & 3, kt + 3);
        CP_COMMIT();
    }

#pragma unroll
    for (int mt = 0; mt < 2; mt++) {
        const int row = rowBase + warpRow + mt * 16 + g;
#pragma unroll
        for (int nt = 0; nt < 8; nt++) {
            const int col = colBase + warpCol + nt * 8 + tg * 2;
            const float2 bv = *(const float2*)(bias + col);
            const float v0 = acc[mt][nt][0] + bv.x, v1 = acc[mt][nt][1] + bv.y;
            const float v2 = acc[mt][nt][2] + bv.x, v3 = acc[mt][nt][3] + bv.y;
            if (sizeof(TOUT) == 2) {
                __half* Ch = (__half*)C;
                const int h = col >> 5, cc = col & 31;
                const int b0 = row >> 13, rem0 = row & (HW_ - 1);
                const int b1 = (row + 8) >> 13, rem1 = (row + 8) & (HW_ - 1);
                *(unsigned*)(Ch + ((size_t)(b0 * NH_ + h) * HW_ + rem0) * 32 + cc) = pack2(v0, v1);
                *(unsigned*)(Ch + ((size_t)(b1 * NH_ + h) * HW_ + rem1) * 32 + cc) = pack2(v2, v3);
            } else {
                float* Cf = (float*)C;
                *(float2*)(Cf + (size_t)row * NDIM + col) = make_float2(v0, v1);
                *(float2*)(Cf + (size_t)(row + 8) * NDIM + col) = make_float2(v2, v3);
            }
        }
    }
#undef ISSUE
}

__global__ __launch_bounds__(256, 2)
void gemm_heads(const float* __restrict__ query, const float* __restrict__ beff,
                float* __restrict__ offA,
                const float* __restrict__ keys0, const float* __restrict__ keys1,
                const float* __restrict__ bk,
                __half* __restrict__ sfh0, __half* __restrict__ sfh1)
{
    extern __shared__ __align__(16) unsigned smem_dyn[];
    if (blockIdx.z == 0)      gemm_core<float, float >(query, g_WeffP, beff, offA, smem_dyn);
    else if (blockIdx.z == 1) gemm_core<float, __half>(keys0, g_WkP, bk, sfh0, smem_dyn);
    else                      gemm_core<float, __half>(keys1, g_WkP, bk, sfh1, smem_dyn);
}

__global__ __launch_bounds__(256, 2)
void gemm_out(const float* __restrict__ bias, float* __restrict__ C)
{
    extern __shared__ __align__(16) unsigned smem_dyn[];
    gemm_core<__half, float>(g_feath, g_WmP, bias, C, smem_dyn);
}

#define SMEM_HEADS (STAGES*(GT<float >::ABUF + BS_BUF)*4)
#define SMEM_OUT   (STAGES*(GT<__half>::ABUF + BS_BUF)*4)

// ------------------------- deformable sampling: two-phase, head-major gathers ---------------
__global__ __launch_bounds__(256)
void sample_kernel(const float* __restrict__ refp)
{
    __shared__ float s_w [4][NH_][8][4];   // (w00, w10, w01, w11): [side][row] pairs
    __shared__ int   s_ix[4][NH_][8][2];

    const int blk = blockIdx.x;
    const int tid = threadIdx.x;

    {
        const int j   = tid & 7;
        const int h   = (tid >> 3) & 7;
        const int sub = tid >> 6;
        const int pixel = blk * 4 + sub;
        const int b = pixel >> 13;
        const int rem = pixel & (HW_ - 1);
        // torch .repeat quirk: ref for bh-index n = b*NH+h is ref_point[n % B]
        const int rb = (b * NH_ + h) % B_;
        const float ry = refp[(rb * HW_ + rem) * 2 + 0];
        const float rx = refp[(rb * HW_ + rem) * 2 + 1];

        const float lgj = g_offA[(size_t)pixel * NOAP + 128 + h * 8 + j];
        float mx = lgj;
#pragma unroll
        for (int o = 4; o; o >>= 1) mx = fmaxf(mx, __shfl_xor_sync(0xffffffffu, mx, o, 8));
        const float e = expf(lgj - mx);
        float s = e;
#pragma unroll
        for (int o = 4; o; o >>= 1) s += __shfl_xor_sync(0xffffffffu, s, o, 8);
        const float w = e / s;

        const float2 off = *(const float2*)(g_offA + (size_t)pixel * NOAP + h * 16 + j * 2);
        const float py = (ry + off.x) * ((float)H_ / (float)(H_ - 1)) - 0.5f;
        const float px = (rx + off.y) * ((float)W_ / (float)(W_ - 1)) - 0.5f;
        const float fy = floorf(py), fx = floorf(px);
        const int y0 = (int)fy, x0 = (int)fx;
        const float wy1 = py - fy, wx1 = px - fx;
        const float wy0 = 1.f - wy1, wx0 = 1.f - wx1;
        const bool yv0 = (y0 >= 0) && (y0 < H_);
        const bool yv1 = (y0 + 1 >= 0) && (y0 + 1 < H_);
        const bool xv0 = (x0 >= 0) && (x0 < W_);
        const bool xv1 = (x0 + 1 >= 0) && (x0 + 1 < W_);
        const int y0c = min(max(y0, 0), H_ - 1), y1c = min(max(y0 + 1, 0), H_ - 1);
        const int xb  = min(max(x0, -1), W_ - 1);
        const int l = j >> 2;
        const int bh = (b * NH_ + h) * HW_;
        const int loff = l * LSTRIDE;
        s_ix[sub][h][j][0] = loff + (bh + y0c * W_ + xb) * 32;
        s_ix[sub][h][j][1] = loff + (bh + y1c * W_ + xb) * 32;
        s_w [sub][h][j][0] = (yv0 && xv0) ? w * wy0 * wx0 : 0.f;
        s_w [sub][h][j][1] = (yv1 && xv0) ? w * wy1 * wx0 : 0.f;
        s_w [sub][h][j][2] = (yv0 && xv1) ? w * wy0 * wx1 : 0.f;
        s_w [sub][h][j][3] = (yv1 && xv1) ? w * wy1 * wx1 : 0.f;
    }
    __syncthreads();

    const int sub = tid >> 6;
    const int h = (tid >> 3) & 7;
    const int e = tid & 7;
    const int pixel = blk * 4 + sub;
    const bool hi = (e >= 4);
    const int ce = e & 3;
    const int ws = hi ? 2 : 0;

    const __half* sfh = g_sfh + 32;

    float acc[8];
#pragma unroll
    for (int i = 0; i < 8; i++) acc[i] = 0.f;

#pragma unroll
    for (int j = 0; j < 8; j++) {
        const float2 wv = *(const float2*)(&s_w[sub][h][j][ws]);
        const int2   i2 = *(const int2*)(s_ix[sub][h][j]);
        const uint4 u0 = *(const uint4*)(sfh + i2.x + e * 8);
        const uint4 u1 = *(const uint4*)(sfh + i2.y + e * 8);
#pragma unroll
        for (int c = 0; c < 4; c++) {
            const float2 f0 = __half22float2(*(const __half2*)(&(&u0.x)[c]));
            const float2 f1 = __half22float2(*(const __half2*)(&(&u1.x)[c]));
            acc[2 * c + 0] += wv.x * f0.x + wv.y * f1.x;
            acc[2 * c + 1] += wv.x * f0.y + wv.y * f1.y;
        }
    }

    unsigned out[4];
#pragma unroll
    for (int c = 0; c < 4; c++) {
        const float s0 = acc[2 * c + 0] + __shfl_xor_sync(0xffffffffu, acc[2 * c + 0], 4);
        const float s1 = acc[2 * c + 1] + __shfl_xor_sync(0xffffffffu, acc[2 * c + 1], 4);
        out[c] = pack2(s0, s1);
    }
    if (!hi) {
        *(uint4*)(g_feath + (size_t)pixel * DM_ + h * 32 + ce * 8)
            = make_uint4(out[0], out[1], out[2], out[3]);
    }
}

// ------------------------- launch -------------------------
extern "C" void kernel_launch(void* const* d_in, const int* in_sizes, int n_in,
                              void* d_out, int out_size)
{
    const float* query = (const float*)d_in[0];
    const float* keys0 = (const float*)d_in[1];
    const float* keys1 = (const float*)d_in[2];
    const float* refp  = (const float*)d_in[3];
    const float* Wq = (const float*)d_in[4];
    const float* bq = (const float*)d_in[5];
    const float* Wk = (const float*)d_in[6];
    const float* bk = (const float*)d_in[7];
    const float* Wo = (const float*)d_in[8];
    const float* bo = (const float*)d_in[9];
    const float* Wa = (const float*)d_in[10];
    const float* ba = (const float*)d_in[11];
    const float* Wm = (const float*)d_in[12];
    const float* bm = (const float*)d_in[13];
    float* out = (float*)d_out;

    __half* sfh;
    float *offA, *beff;
    cudaGetSymbolAddress((void**)&sfh,  g_sfh);
    cudaGetSymbolAddress((void**)&offA, g_offA);
    cudaGetSymbolAddress((void**)&beff, g_beff);
    __half* sfh0 = sfh + 32;
    __half* sfh1 = sfh + 32 + LSTRIDE;

    cudaFuncSetAttribute(gemm_heads, cudaFuncAttributeMaxDynamicSharedMemorySize, SMEM_HEADS);
    cudaFuncSetAttribute(gemm_out,   cudaFuncAttributeMaxDynamicSharedMemorySize, SMEM_OUT);

    prep_kernel<<<385, 256>>>(Wq, Wo, Wa, bq, bo, ba, Wk, Wm);

    dim3 gh(NDIM / 128, NPIX / 128, 3);
    gemm_heads<<<gh, 256, SMEM_HEADS>>>(query, beff, offA, keys0, keys1, bk, sfh0, sfh1);

    sample_kernel<<<NPIX / 4, 256>>>(refp);

    dim3 gg(NDIM / 128, NPIX / 128);
    gemm_out<<<gg, 256, SMEM_OUT>>>(bm, out);

    (void)in_sizes; (void)n_in; (void)out_size;
}